// round 12
// baseline (speedup 1.0000x reference)
#include <cuda_runtime.h>

// Problem constants (VisualPromptEncoder_49074296324730)
#define BB    8
#define CC    256
#define HH    160
#define WW    160
#define NN    100    // boxes per image
#define NCLS  80     // classes
#define NBAND 8
#define BAND  20     // rows per band
#define PSTR  164    // padded row stride (mult of 4, conflict-free)
#define THRK1 160    // 5 warps

// Band partial sums: [b][band][n][c]
__device__ float g_partial[BB * NBAND * NN * CC];

// ---------------------------------------------------------------------------
// Kernel 1: one block per (plane, band). Rowscan 20 rows (register scan from
// coalesced LDG, single STS), in-band column scan (chain length 20, in-place,
// exactly one thread per column), SAT lookups -> contiguous partial write.
// ---------------------------------------------------------------------------
__global__ void __launch_bounds__(THRK1, 12)
band_kernel(const float* __restrict__ feat,
            const float* __restrict__ boxes,
            const int*   __restrict__ img_h,
            const int*   __restrict__ img_w)
{
    __shared__ float buf[BAND * PSTR];     // scanned rows -> band SAT (13.1KB)
    __shared__ short sx1[NN], sx2[NN], sy1[NN], sy2[NN];

    const int blk   = blockIdx.x;          // (b*CC + c)*NBAND + band
    const int plane = blk >> 3;
    const int band  = blk & 7;
    const int b     = plane >> 8;
    const int c     = plane & 255;
    const int tid   = threadIdx.x;         // 0..159
    const int w     = tid >> 5;            // warp 0..4
    const int lane  = tid & 31;
    const int lo    = band * BAND;
    const int hi    = lo + BAND;

    // ---- box coords ----
    if (tid < NN) {
        const float sxf = (float)WW / (float)img_w[0];
        const float syf = (float)HH / (float)img_h[0];
        const float* bx = boxes + ((size_t)b * NN + tid) * 4;
        sx1[tid] = (short)(int)fminf(fmaxf(floorf(bx[0] * sxf), 0.f), (float)WW);
        sy1[tid] = (short)(int)fminf(fmaxf(floorf(bx[1] * syf), 0.f), (float)HH);
        sx2[tid] = (short)(int)fminf(fmaxf(floorf(bx[2] * sxf), 0.f), (float)WW);
        sy2[tid] = (short)(int)fminf(fmaxf(floorf(bx[3] * syf), 0.f), (float)HH);
    }

    // ---- row scan: warp w handles local rows w+5q (q=0..3) ----
    const float4* plane4 = (const float4*)(feat + (size_t)plane * (HH * WW));
    #pragma unroll
    for (int q = 0; q < 4; q++) {
        const int r = w + 5 * q;                       // local row 0..19
        const float4* row4 = plane4 + (size_t)(lo + r) * 40;
        float4 a  = row4[lane];
        float4 bbv = (lane < 8) ? row4[32 + lane]
                                : make_float4(0.f, 0.f, 0.f, 0.f);
        a.y += a.x; a.z += a.y; a.w += a.z;
        bbv.y += bbv.x; bbv.z += bbv.y; bbv.w += bbv.z;
        const float ta = a.w, tb = bbv.w;
        float ia = ta;
        #pragma unroll
        for (int d = 1; d < 32; d <<= 1) {
            const float o = __shfl_up_sync(0xffffffffu, ia, d);
            if (lane >= d) ia += o;
        }
        const float ea = ia - ta;
        const float T0 = __shfl_sync(0xffffffffu, ia, 31);
        float ib = tb;
        #pragma unroll
        for (int d = 1; d < 8; d <<= 1) {
            const float o = __shfl_up_sync(0xffffffffu, ib, d);
            if (lane >= d) ib += o;
        }
        const float eb = T0 + (ib - tb);
        float* dst = &buf[r * PSTR];
        *(float4*)&dst[4 * lane] =
            make_float4(a.x + ea, a.y + ea, a.z + ea, a.w + ea);
        if (lane < 8)
            *(float4*)&dst[128 + 4 * lane] =
                make_float4(bbv.x + eb, bbv.y + eb, bbv.z + eb, bbv.w + eb);
    }
    __syncthreads();

    // ---- in-band column scan (in-place): thread tid owns column tid ----
    {
        float run0 = 0.f;
        #pragma unroll
        for (int r = 0; r < BAND; r++) {
            const int idx = r * PSTR + tid;
            run0 += buf[idx];
            buf[idx] = run0;
        }
    }
    __syncthreads();

    // ---- per-box band partial: up to 4 SAT lookups ----
    if (tid < NN) {
        const int x1 = sx1[tid], x2 = sx2[tid];
        const int y1 = sy1[tid], y2 = sy2[tid];
        float partial = 0.f;
        if (x2 > x1 && y2 > y1) {
            const int a0 = (y1 > lo) ? y1 : lo;       // first row in band
            const int b0 = (y2 < hi) ? y2 : hi;       // one past last
            if (a0 < b0) {
                const int rb = b0 - 1 - lo;           // 0..19
                float v = buf[rb * PSTR + (x2 - 1)];
                if (x1 > 0) v -= buf[rb * PSTR + (x1 - 1)];
                if (a0 > lo) {
                    const int rt = a0 - 1 - lo;
                    float u = buf[rt * PSTR + (x2 - 1)];
                    if (x1 > 0) u -= buf[rt * PSTR + (x1 - 1)];
                    v -= u;
                }
                partial = v;
            }
        }
        g_partial[(((size_t)b * NBAND + band) * NN + tid) * CC + c] = partial;
    }
}

// ---------------------------------------------------------------------------
// Kernel 2: per (b, cls) — sum band partials / area, class mean, neg fallback
// grid = B*NCLS blocks, 256 threads (one per channel).
// ---------------------------------------------------------------------------
__global__ void __launch_bounds__(256)
reduce_kernel(const float* __restrict__ feat,
              const float* __restrict__ boxes,
              const int*   __restrict__ gtc,
              const int*   __restrict__ neg_y,
              const int*   __restrict__ neg_x,
              const int*   __restrict__ img_h,
              const int*   __restrict__ img_w,
              float*       __restrict__ out)
{
    const int blk  = blockIdx.x;           // b*NCLS + cls
    const int b    = blk / NCLS;
    const int cls  = blk - b * NCLS;
    const int c    = threadIdx.x;          // 0..255
    const int w    = c >> 5;
    const int lane = c & 31;

    __shared__ int   s_idx[NN];
    __shared__ float s_inva[NN];           // 1/area for matched boxes
    __shared__ int   s_wcnt[8];

    bool match = false;
    float inva = 0.f;
    if (c < NN) {
        const int cl = gtc[b * NN + c];
        const float sxf = (float)WW / (float)img_w[0];
        const float syf = (float)HH / (float)img_h[0];
        const float* bx = boxes + ((size_t)b * NN + c) * 4;
        const int x1 = (int)fminf(fmaxf(floorf(bx[0] * sxf), 0.f), (float)WW);
        const int y1 = (int)fminf(fmaxf(floorf(bx[1] * syf), 0.f), (float)HH);
        const int x2 = (int)fminf(fmaxf(floorf(bx[2] * sxf), 0.f), (float)WW);
        const int y2 = (int)fminf(fmaxf(floorf(bx[3] * syf), 0.f), (float)HH);
        match = (cl == cls) && (x2 > x1) && (y2 > y1);
        if (match) {
            int area = (x2 - x1) * (y2 - y1);
            if (area < 1) area = 1;
            inva = 1.f / (float)area;
        }
    }
    const unsigned m = __ballot_sync(0xffffffffu, match);
    if (lane == 0) s_wcnt[w] = __popc(m);
    __syncthreads();

    int woff = 0, total = 0;
    #pragma unroll
    for (int j = 0; j < 8; j++) {
        const int wc = s_wcnt[j];
        woff  += (j < w) ? wc : 0;
        total += wc;
    }
    if (match) {
        const int pos = woff + __popc(m & ((1u << lane) - 1u));
        s_idx[pos]  = c;
        s_inva[pos] = inva;
    }
    __syncthreads();

    float r;
    if (total > 0) {
        float sum = 0.f;
        for (int i = 0; i < total; i++) {
            const int n = s_idx[i];
            const float* pp = g_partial + ((size_t)b * NBAND * NN + n) * CC + c;
            float s = 0.f;
            #pragma unroll
            for (int band = 0; band < NBAND; band++)
                s += pp[(size_t)band * NN * CC];
            sum += s * s_inva[i];
        }
        r = sum / (float)total;
    } else {
        const int ny = neg_y[b * NCLS + cls];
        const int nx = neg_x[b * NCLS + cls];
        r = feat[(((size_t)b * CC + c) * HH + ny) * WW + nx];
    }
    out[(size_t)blk * CC + c] = r;
}

// ---------------------------------------------------------------------------
extern "C" void kernel_launch(void* const* d_in, const int* in_sizes, int n_in,
                              void* d_out, int out_size)
{
    const float* feat  = (const float*)d_in[0];   // [8,256,160,160] f32
    const float* boxes = (const float*)d_in[1];   // [8,100,4] f32
    const int*   gtc   = (const int*)d_in[2];     // [8,100] i32
    const int*   ngy   = (const int*)d_in[3];     // [8,80] i32
    const int*   ngx   = (const int*)d_in[4];     // [8,80] i32
    const int*   ih    = (const int*)d_in[5];     // scalar
    const int*   iw    = (const int*)d_in[6];     // scalar
    float*       out   = (float*)d_out;           // [8,80,256] f32

    band_kernel<<<BB * CC * NBAND, THRK1>>>(feat, boxes, ih, iw);
    reduce_kernel<<<BB * NCLS, 256>>>(feat, boxes, gtc, ngy, ngx, ih, iw, out);
}

// round 13
// speedup vs baseline: 1.1020x; 1.1020x over previous
#include <cuda_runtime.h>

// Problem constants (VisualPromptEncoder_49074296324730)
#define BB    8
#define CC    256
#define HH    160
#define WW    160
#define NN    100    // boxes per image
#define NCLS  80     // classes
#define NBAND 4
#define BAND  40     // rows per band
#define PSTR  164    // padded row stride (mult of 4, conflict-free)
#define THRK1 128    // 4 warps

// Band partial sums: [b][band][n][c]
__device__ float g_partial[BB * NBAND * NN * CC];

// ---------------------------------------------------------------------------
// Kernel 1: one block per (plane, band). Register row scan from coalesced LDG
// with depth-1 software prefetch (fits in the 64-reg budget at 8 blocks/SM),
// in-band column scan (chain 40), SAT lookups -> contiguous partial write.
// ---------------------------------------------------------------------------
__global__ void __launch_bounds__(THRK1, 8)
band_kernel(const float* __restrict__ feat,
            const float* __restrict__ boxes,
            const int*   __restrict__ img_h,
            const int*   __restrict__ img_w)
{
    __shared__ float buf[BAND * PSTR];     // scanned rows -> band SAT (26.2KB)
    __shared__ short sx1[NN], sx2[NN], sy1[NN], sy2[NN];

    const int blk   = blockIdx.x;          // (b*CC + c)*NBAND + band
    const int plane = blk >> 2;
    const int band  = blk & 3;
    const int b     = plane >> 8;
    const int c     = plane & 255;
    const int tid   = threadIdx.x;         // 0..127
    const int w     = tid >> 5;            // warp 0..3
    const int lane  = tid & 31;
    const int lo    = band * BAND;
    const int hi    = lo + BAND;

    const float4* plane4 = (const float4*)(feat + (size_t)plane * (HH * WW));

    // ---- issue first row's loads immediately (setup below covers latency) ----
    float4 a, bbv;
    {
        const float4* row4 = plane4 + (size_t)(lo + w) * 40;
        a   = row4[lane];
        bbv = (lane < 8) ? row4[32 + lane] : make_float4(0.f, 0.f, 0.f, 0.f);
    }

    // ---- box coords ----
    if (tid < NN) {
        const float sxf = (float)WW / (float)img_w[0];
        const float syf = (float)HH / (float)img_h[0];
        const float* bx = boxes + ((size_t)b * NN + tid) * 4;
        sx1[tid] = (short)(int)fminf(fmaxf(floorf(bx[0] * sxf), 0.f), (float)WW);
        sy1[tid] = (short)(int)fminf(fmaxf(floorf(bx[1] * syf), 0.f), (float)HH);
        sx2[tid] = (short)(int)fminf(fmaxf(floorf(bx[2] * sxf), 0.f), (float)WW);
        sy2[tid] = (short)(int)fminf(fmaxf(floorf(bx[3] * syf), 0.f), (float)HH);
    }

    // ---- row scan: warp w handles local rows w+4q (q=0..9), prefetch q+1 ----
    #pragma unroll
    for (int q = 0; q < 10; q++) {
        const int r = w + 4 * q;                       // local row 0..39

        // prefetch next row before processing current one
        float4 an, bn;
        if (q < 9) {
            const float4* row4n = plane4 + (size_t)(lo + r + 4) * 40;
            an = row4n[lane];
            bn = (lane < 8) ? row4n[32 + lane] : make_float4(0.f, 0.f, 0.f, 0.f);
        }

        a.y += a.x; a.z += a.y; a.w += a.z;
        bbv.y += bbv.x; bbv.z += bbv.y; bbv.w += bbv.z;
        const float ta = a.w, tb = bbv.w;
        float ia = ta;
        #pragma unroll
        for (int d = 1; d < 32; d <<= 1) {
            const float o = __shfl_up_sync(0xffffffffu, ia, d);
            if (lane >= d) ia += o;
        }
        const float ea = ia - ta;
        const float T0 = __shfl_sync(0xffffffffu, ia, 31);
        float ib = tb;
        #pragma unroll
        for (int d = 1; d < 8; d <<= 1) {
            const float o = __shfl_up_sync(0xffffffffu, ib, d);
            if (lane >= d) ib += o;
        }
        const float eb = T0 + (ib - tb);
        float* dst = &buf[r * PSTR];
        *(float4*)&dst[4 * lane] =
            make_float4(a.x + ea, a.y + ea, a.z + ea, a.w + ea);
        if (lane < 8)
            *(float4*)&dst[128 + 4 * lane] =
                make_float4(bbv.x + eb, bbv.y + eb, bbv.z + eb, bbv.w + eb);

        a = an; bbv = bn;
    }
    __syncthreads();

    // ---- in-band column scan (in-place). thread owns col tid; warp 0 also
    //      owns col 128+tid. Branch-free chains of length 40. ----
    {
        float run0 = 0.f;
        #pragma unroll 8
        for (int r = 0; r < BAND; r++) {
            const int idx = r * PSTR + tid;
            run0 += buf[idx];
            buf[idx] = run0;
        }
        if (tid < 32) {
            float run1 = 0.f;
            #pragma unroll 8
            for (int r = 0; r < BAND; r++) {
                const int idx = r * PSTR + 128 + tid;
                run1 += buf[idx];
                buf[idx] = run1;
            }
        }
    }
    __syncthreads();

    // ---- per-box band partial: up to 4 SAT lookups ----
    if (tid < NN) {
        const int x1 = sx1[tid], x2 = sx2[tid];
        const int y1 = sy1[tid], y2 = sy2[tid];
        float partial = 0.f;
        if (x2 > x1 && y2 > y1) {
            const int a0 = (y1 > lo) ? y1 : lo;       // first row in band
            const int b0 = (y2 < hi) ? y2 : hi;       // one past last
            if (a0 < b0) {
                const int rb = b0 - 1 - lo;           // 0..39
                float v = buf[rb * PSTR + (x2 - 1)];
                if (x1 > 0) v -= buf[rb * PSTR + (x1 - 1)];
                if (a0 > lo) {
                    const int rt = a0 - 1 - lo;
                    float u = buf[rt * PSTR + (x2 - 1)];
                    if (x1 > 0) u -= buf[rt * PSTR + (x1 - 1)];
                    v -= u;
                }
                partial = v;
            }
        }
        g_partial[(((size_t)b * NBAND + band) * NN + tid) * CC + c] = partial;
    }
}

// ---------------------------------------------------------------------------
// Kernel 2: per (b, cls) — sum band partials / area, class mean, neg fallback
// grid = B*NCLS blocks, 256 threads (one per channel). Coalesced loads.
// ---------------------------------------------------------------------------
__global__ void __launch_bounds__(256)
reduce_kernel(const float* __restrict__ feat,
              const float* __restrict__ boxes,
              const int*   __restrict__ gtc,
              const int*   __restrict__ neg_y,
              const int*   __restrict__ neg_x,
              const int*   __restrict__ img_h,
              const int*   __restrict__ img_w,
              float*       __restrict__ out)
{
    const int blk  = blockIdx.x;           // b*NCLS + cls
    const int b    = blk / NCLS;
    const int cls  = blk - b * NCLS;
    const int c    = threadIdx.x;          // 0..255
    const int w    = c >> 5;
    const int lane = c & 31;

    __shared__ int   s_idx[NN];
    __shared__ float s_inva[NN];           // 1/area for matched boxes
    __shared__ int   s_wcnt[8];

    bool match = false;
    float inva = 0.f;
    if (c < NN) {
        const int cl = gtc[b * NN + c];
        const float sxf = (float)WW / (float)img_w[0];
        const float syf = (float)HH / (float)img_h[0];
        const float* bx = boxes + ((size_t)b * NN + c) * 4;
        const int x1 = (int)fminf(fmaxf(floorf(bx[0] * sxf), 0.f), (float)WW);
        const int y1 = (int)fminf(fmaxf(floorf(bx[1] * syf), 0.f), (float)HH);
        const int x2 = (int)fminf(fmaxf(floorf(bx[2] * sxf), 0.f), (float)WW);
        const int y2 = (int)fminf(fmaxf(floorf(bx[3] * syf), 0.f), (float)HH);
        match = (cl == cls) && (x2 > x1) && (y2 > y1);
        if (match) {
            int area = (x2 - x1) * (y2 - y1);
            if (area < 1) area = 1;
            inva = 1.f / (float)area;
        }
    }
    const unsigned m = __ballot_sync(0xffffffffu, match);
    if (lane == 0) s_wcnt[w] = __popc(m);
    __syncthreads();

    int woff = 0, total = 0;
    #pragma unroll
    for (int j = 0; j < 8; j++) {
        const int wc = s_wcnt[j];
        woff  += (j < w) ? wc : 0;
        total += wc;
    }
    if (match) {
        const int pos = woff + __popc(m & ((1u << lane) - 1u));
        s_idx[pos]  = c;
        s_inva[pos] = inva;
    }
    __syncthreads();

    float r;
    if (total > 0) {
        float sum = 0.f;
        for (int i = 0; i < total; i++) {
            const int n = s_idx[i];
            const float* pp = g_partial + ((size_t)b * NBAND * NN + n) * CC + c;
            float s = 0.f;
            #pragma unroll
            for (int band = 0; band < NBAND; band++)
                s += pp[(size_t)band * NN * CC];
            sum += s * s_inva[i];
        }
        r = sum / (float)total;
    } else {
        const int ny = neg_y[b * NCLS + cls];
        const int nx = neg_x[b * NCLS + cls];
        r = feat[(((size_t)b * CC + c) * HH + ny) * WW + nx];
    }
    out[(size_t)blk * CC + c] = r;
}

// ---------------------------------------------------------------------------
extern "C" void kernel_launch(void* const* d_in, const int* in_sizes, int n_in,
                              void* d_out, int out_size)
{
    const float* feat  = (const float*)d_in[0];   // [8,256,160,160] f32
    const float* boxes = (const float*)d_in[1];   // [8,100,4] f32
    const int*   gtc   = (const int*)d_in[2];     // [8,100] i32
    const int*   ngy   = (const int*)d_in[3];     // [8,80] i32
    const int*   ngx   = (const int*)d_in[4];     // [8,80] i32
    const int*   ih    = (const int*)d_in[5];     // scalar
    const int*   iw    = (const int*)d_in[6];     // scalar
    float*       out   = (float*)d_out;           // [8,80,256] f32

    band_kernel<<<BB * CC * NBAND, THRK1>>>(feat, boxes, ih, iw);
    reduce_kernel<<<BB * NCLS, 256>>>(feat, boxes, gtc, ngy, ngx, ih, iw, out);
}

// round 14
// speedup vs baseline: 1.1056x; 1.0032x over previous
#include <cuda_runtime.h>

// Problem constants (VisualPromptEncoder_49074296324730)
#define BB    8
#define CC    256
#define HH    160
#define WW    160
#define NN    100    // boxes per image
#define NCLS  80     // classes
#define NBAND 4
#define BAND  40     // rows per band
#define PSTR  164    // padded row stride (mult of 4, conflict-free)
#define THRK1 160    // 5 warps

// Band partial sums: [b][band][n][c]
__device__ float g_partial[BB * NBAND * NN * CC];

// ---------------------------------------------------------------------------
// Kernel 1: one block per (plane, band). Register row scan from coalesced LDG
// with depth-1 software prefetch; balanced in-band column scan (exactly one
// column per thread, chain 40); SAT lookups -> contiguous partial write.
// ---------------------------------------------------------------------------
__global__ void __launch_bounds__(THRK1, 8)
band_kernel(const float* __restrict__ feat,
            const float* __restrict__ boxes,
            const int*   __restrict__ img_h,
            const int*   __restrict__ img_w)
{
    __shared__ float buf[BAND * PSTR];     // scanned rows -> band SAT (26.2KB)
    __shared__ short sx1[NN], sx2[NN], sy1[NN], sy2[NN];

    const int blk   = blockIdx.x;          // (b*CC + c)*NBAND + band
    const int plane = blk >> 2;
    const int band  = blk & 3;
    const int b     = plane >> 8;
    const int c     = plane & 255;
    const int tid   = threadIdx.x;         // 0..159
    const int w     = tid >> 5;            // warp 0..4
    const int lane  = tid & 31;
    const int lo    = band * BAND;
    const int hi    = lo + BAND;

    const float4* plane4 = (const float4*)(feat + (size_t)plane * (HH * WW));

    // ---- issue first row's loads immediately (setup below covers latency) ----
    float4 a, bbv;
    {
        const float4* row4 = plane4 + (size_t)(lo + w) * 40;
        a   = row4[lane];
        bbv = (lane < 8) ? row4[32 + lane] : make_float4(0.f, 0.f, 0.f, 0.f);
    }

    // ---- box coords ----
    if (tid < NN) {
        const float sxf = (float)WW / (float)img_w[0];
        const float syf = (float)HH / (float)img_h[0];
        const float* bx = boxes + ((size_t)b * NN + tid) * 4;
        sx1[tid] = (short)(int)fminf(fmaxf(floorf(bx[0] * sxf), 0.f), (float)WW);
        sy1[tid] = (short)(int)fminf(fmaxf(floorf(bx[1] * syf), 0.f), (float)HH);
        sx2[tid] = (short)(int)fminf(fmaxf(floorf(bx[2] * sxf), 0.f), (float)WW);
        sy2[tid] = (short)(int)fminf(fmaxf(floorf(bx[3] * syf), 0.f), (float)HH);
    }

    // ---- row scan: warp w handles local rows w+5q (q=0..7), prefetch q+1 ----
    #pragma unroll
    for (int q = 0; q < 8; q++) {
        const int r = w + 5 * q;                       // local row 0..39

        // prefetch next row before processing current one
        float4 an, bn;
        if (q < 7) {
            const float4* row4n = plane4 + (size_t)(lo + r + 5) * 40;
            an = row4n[lane];
            bn = (lane < 8) ? row4n[32 + lane] : make_float4(0.f, 0.f, 0.f, 0.f);
        }

        a.y += a.x; a.z += a.y; a.w += a.z;
        bbv.y += bbv.x; bbv.z += bbv.y; bbv.w += bbv.z;
        const float ta = a.w, tb = bbv.w;
        float ia = ta;
        #pragma unroll
        for (int d = 1; d < 32; d <<= 1) {
            const float o = __shfl_up_sync(0xffffffffu, ia, d);
            if (lane >= d) ia += o;
        }
        const float ea = ia - ta;
        const float T0 = __shfl_sync(0xffffffffu, ia, 31);
        float ib = tb;
        #pragma unroll
        for (int d = 1; d < 8; d <<= 1) {
            const float o = __shfl_up_sync(0xffffffffu, ib, d);
            if (lane >= d) ib += o;
        }
        const float eb = T0 + (ib - tb);
        float* dst = &buf[r * PSTR];
        *(float4*)&dst[4 * lane] =
            make_float4(a.x + ea, a.y + ea, a.z + ea, a.w + ea);
        if (lane < 8)
            *(float4*)&dst[128 + 4 * lane] =
                make_float4(bbv.x + eb, bbv.y + eb, bbv.z + eb, bbv.w + eb);

        a = an; bbv = bn;
    }
    __syncthreads();

    // ---- in-band column scan (in-place): exactly one column per thread ----
    {
        float run0 = 0.f;
        #pragma unroll 8
        for (int r = 0; r < BAND; r++) {
            const int idx = r * PSTR + tid;
            run0 += buf[idx];
            buf[idx] = run0;
        }
    }
    __syncthreads();

    // ---- per-box band partial: up to 4 SAT lookups ----
    if (tid < NN) {
        const int x1 = sx1[tid], x2 = sx2[tid];
        const int y1 = sy1[tid], y2 = sy2[tid];
        float partial = 0.f;
        if (x2 > x1 && y2 > y1) {
            const int a0 = (y1 > lo) ? y1 : lo;       // first row in band
            const int b0 = (y2 < hi) ? y2 : hi;       // one past last
            if (a0 < b0) {
                const int rb = b0 - 1 - lo;           // 0..39
                float v = buf[rb * PSTR + (x2 - 1)];
                if (x1 > 0) v -= buf[rb * PSTR + (x1 - 1)];
                if (a0 > lo) {
                    const int rt = a0 - 1 - lo;
                    float u = buf[rt * PSTR + (x2 - 1)];
                    if (x1 > 0) u -= buf[rt * PSTR + (x1 - 1)];
                    v -= u;
                }
                partial = v;
            }
        }
        g_partial[(((size_t)b * NBAND + band) * NN + tid) * CC + c] = partial;
    }
}

// ---------------------------------------------------------------------------
// Kernel 2: per (b, cls) — sum band partials / area, class mean, neg fallback
// grid = B*NCLS blocks, 256 threads (one per channel). Coalesced loads.
// ---------------------------------------------------------------------------
__global__ void __launch_bounds__(256)
reduce_kernel(const float* __restrict__ feat,
              const float* __restrict__ boxes,
              const int*   __restrict__ gtc,
              const int*   __restrict__ neg_y,
              const int*   __restrict__ neg_x,
              const int*   __restrict__ img_h,
              const int*   __restrict__ img_w,
              float*       __restrict__ out)
{
    const int blk  = blockIdx.x;           // b*NCLS + cls
    const int b    = blk / NCLS;
    const int cls  = blk - b * NCLS;
    const int c    = threadIdx.x;          // 0..255
    const int w    = c >> 5;
    const int lane = c & 31;

    __shared__ int   s_idx[NN];
    __shared__ float s_inva[NN];           // 1/area for matched boxes
    __shared__ int   s_wcnt[8];

    bool match = false;
    float inva = 0.f;
    if (c < NN) {
        const int cl = gtc[b * NN + c];
        const float sxf = (float)WW / (float)img_w[0];
        const float syf = (float)HH / (float)img_h[0];
        const float* bx = boxes + ((size_t)b * NN + c) * 4;
        const int x1 = (int)fminf(fmaxf(floorf(bx[0] * sxf), 0.f), (float)WW);
        const int y1 = (int)fminf(fmaxf(floorf(bx[1] * syf), 0.f), (float)HH);
        const int x2 = (int)fminf(fmaxf(floorf(bx[2] * sxf), 0.f), (float)WW);
        const int y2 = (int)fminf(fmaxf(floorf(bx[3] * syf), 0.f), (float)HH);
        match = (cl == cls) && (x2 > x1) && (y2 > y1);
        if (match) {
            int area = (x2 - x1) * (y2 - y1);
            if (area < 1) area = 1;
            inva = 1.f / (float)area;
        }
    }
    const unsigned m = __ballot_sync(0xffffffffu, match);
    if (lane == 0) s_wcnt[w] = __popc(m);
    __syncthreads();

    int woff = 0, total = 0;
    #pragma unroll
    for (int j = 0; j < 8; j++) {
        const int wc = s_wcnt[j];
        woff  += (j < w) ? wc : 0;
        total += wc;
    }
    if (match) {
        const int pos = woff + __popc(m & ((1u << lane) - 1u));
        s_idx[pos]  = c;
        s_inva[pos] = inva;
    }
    __syncthreads();

    float r;
    if (total > 0) {
        float sum = 0.f;
        for (int i = 0; i < total; i++) {
            const int n = s_idx[i];
            const float* pp = g_partial + ((size_t)b * NBAND * NN + n) * CC + c;
            float s = 0.f;
            #pragma unroll
            for (int band = 0; band < NBAND; band++)
                s += pp[(size_t)band * NN * CC];
            sum += s * s_inva[i];
        }
        r = sum / (float)total;
    } else {
        const int ny = neg_y[b * NCLS + cls];
        const int nx = neg_x[b * NCLS + cls];
        r = feat[(((size_t)b * CC + c) * HH + ny) * WW + nx];
    }
    out[(size_t)blk * CC + c] = r;
}

// ---------------------------------------------------------------------------
extern "C" void kernel_launch(void* const* d_in, const int* in_sizes, int n_in,
                              void* d_out, int out_size)
{
    const float* feat  = (const float*)d_in[0];   // [8,256,160,160] f32
    const float* boxes = (const float*)d_in[1];   // [8,100,4] f32
    const int*   gtc   = (const int*)d_in[2];     // [8,100] i32
    const int*   ngy   = (const int*)d_in[3];     // [8,80] i32
    const int*   ngx   = (const int*)d_in[4];     // [8,80] i32
    const int*   ih    = (const int*)d_in[5];     // scalar
    const int*   iw    = (const int*)d_in[6];     // scalar
    float*       out   = (float*)d_out;           // [8,80,256] f32

    band_kernel<<<BB * CC * NBAND, THRK1>>>(feat, boxes, ih, iw);
    reduce_kernel<<<BB * NCLS, 256>>>(feat, boxes, gtc, ngy, ngx, ih, iw, out);
}